// round 5
// baseline (speedup 1.0000x reference)
#include <cuda_runtime.h>
#include <cuda_bf16.h>
#include <math.h>
#include <stdint.h>

#define NN 100000
#define NE 1000000
#define D  64
#define H  128
#define NL 4
#define NG 64
#define TILE_E 128
#define NT ((NE + TILE_E - 1) / TILE_E)   // 7813
#define EGRID 148
#define ETHREADS 512
#define M1P 129   // ull pitch, edge-major

typedef unsigned long long ull;

// ---------------- persistent device scratch ----------------
__device__ float g_h[NN * D];
__device__ float g_PQ[NN * 256];     // P (cols 0..127) | Q (cols 128..255)
__device__ float g_agg[NN * D];
__device__ float g_rbf[(size_t)NE * 16];
__device__ int   g_kind[NE];
__device__ float g_kt[NL * 2 * H];
__device__ float g_sums[NG * D];
__device__ float g_cnt[NG];

// ---------------- f32x2 helpers ----------------
#define PACK2(d, x, y) asm("mov.b64 %0, {%1,%2};" : "=l"(d) : "r"(__float_as_uint(x)), "r"(__float_as_uint(y)))
#define UNPK2(lo, hi, v) asm("mov.b64 {%0,%1}, %2;" : "=r"(lo), "=r"(hi) : "l"(v))
#define FMA2(acc, a, b) asm("fma.rn.f32x2 %0, %1, %2, %0;" : "+l"(acc) : "l"(a), "l"(b))
#define ADD2(d, a, b)   asm("add.rn.f32x2 %0, %1, %2;" : "=l"(d) : "l"(a), "l"(b))
#define REDV4(p, v0, v1, v2, v3) \
    asm volatile("red.global.add.v4.f32 [%0], {%1,%2,%3,%4};" \
        :: "l"(p), "f"(v0), "f"(v1), "f"(v2), "f"(v3) : "memory")

// ---------------- init: node embed + zero everything ----------------
__global__ void k_init_h(const int* __restrict__ atoms, const float* __restrict__ embed) {
    int i = blockIdx.x * blockDim.x + threadIdx.x;
    if (i < NN * D) {
        g_h[i] = embed[atoms[i >> 6] * D + (i & 63)];
        g_agg[i] = 0.f;
    }
    if (i < NG * D) g_sums[i] = 0.f;
    if (i < NG) g_cnt[i] = 0.f;
}

// ---------------- edge prep + kind-table (fused) ----------------
__global__ void k_edge_prep(const int* __restrict__ ei, const float* __restrict__ coord,
                            const int* __restrict__ isr,
                            const float* __restrict__ subw, const float* __restrict__ W1,
                            const float* __restrict__ b1) {
    int e = blockIdx.x * blockDim.x + threadIdx.x;
    if (e < NE) {
        int s = ei[e], d = ei[NE + e];
        float dx = coord[s * 3 + 0] - coord[d * 3 + 0];
        float dy = coord[s * 3 + 1] - coord[d * 3 + 1];
        float dz = coord[s * 3 + 2] - coord[d * 3 + 2];
        float dist = sqrtf(dx * dx + dy * dy + dz * dz);
        const float coeff = -4.5f;
        float o[16];
#pragma unroll
        for (int g = 0; g < 16; g++) {
            float t = dist - (float)g * (5.0f / 15.0f);
            o[g] = __expf(coeff * t * t);
        }
        float4* dp = (float4*)&g_rbf[(size_t)e * 16];
        dp[0] = make_float4(o[0], o[1], o[2], o[3]);
        dp[1] = make_float4(o[4], o[5], o[6], o[7]);
        dp[2] = make_float4(o[8], o[9], o[10], o[11]);
        dp[3] = make_float4(o[12], o[13], o[14], o[15]);
        g_kind[e] = (isr[s] != isr[d]) ? 1 : 0;
    } else {
        int t = e - NE;
        if (t < NL * 2 * H) {
            int l = t >> 8, kind = (t >> 7) & 1, j = t & 127;
            const float* W1l = W1 + (size_t)l * 160 * H;
            float v = b1[l * H + j];
#pragma unroll
            for (int g = 0; g < 16; g++)
                v += subw[kind * 16 + g] * W1l[(144 + g) * H + j];
            g_kt[t] = v;
        }
    }
}

// ---------------- node GEMM (R3 shape) + fused relu(h+agg) ----------------
__global__ __launch_bounds__(256) void k_nodegemm(const float* __restrict__ W1, int l) {
    __shared__ float sW[64 * H];
    __shared__ float sh[64 * 18];
    const float* W1l = W1 + (size_t)l * 160 * H;
    int tid = threadIdx.x;
    int n0 = blockIdx.x * 16;
    for (int i = tid; i < 16 * 64; i += 256) {
        int k = i & 63, e = i >> 6;
        size_t idx = (size_t)(n0 + e) * D + k;
        float hv = g_h[idx];
        if (l > 0) {
            hv = fmaxf(hv + g_agg[idx], 0.f);
            g_h[idx] = hv;
            g_agg[idx] = 0.f;
        }
        sh[k * 18 + e] = hv;
    }
    int j = tid & 127;
    int ng = tid >> 7;
    for (int pass = 0; pass < 2; pass++) {
        __syncthreads();
        for (int i = tid; i < 64 * H; i += 256) sW[i] = W1l[pass * 64 * H + i];
        __syncthreads();
        ull acc[4];
#pragma unroll
        for (int q = 0; q < 4; q++) acc[q] = 0ull;
#pragma unroll 8
        for (int k = 0; k < 64; k++) {
            float w = sW[k * H + j];
            ull ww; PACK2(ww, w, w);
#pragma unroll
            for (int q = 0; q < 4; q++) {
                ull hv = *(const ull*)&sh[k * 18 + ng * 8 + q * 2];
                FMA2(acc[q], hv, ww);
            }
        }
#pragma unroll
        for (int q = 0; q < 4; q++) {
            uint32_t lo, hi; UNPK2(lo, hi, acc[q]);
            int nb = n0 + ng * 8 + q * 2;
            g_PQ[(size_t)nb * 256 + pass * 128 + j] = __uint_as_float(lo);
            g_PQ[(size_t)(nb + 1) * 256 + pass * 128 + j] = __uint_as_float(hi);
        }
    }
}

// ---------------- fused persistent edge kernel ----------------
// smem byte offsets
#define OFF_M1   0         // ull[128][129] = 132096  (edge-major, values duplicated)
#define OFF_W2   132096    // float[128*64] = 32768
#define OFF_RBF  164864    // ull[128*16] = 16384 (duplicated)
#define OFF_W1C  181248    // float[16*128] = 8192
#define OFF_KT   189440    // 1024
#define OFF_B2   190464    // 256
#define OFF_DST  190720    // 512
#define OFF_SRC  191232    // 512
#define OFF_KND  191744    // 512
#define SMEM_EDGE 192256

__global__ __launch_bounds__(ETHREADS, 1) void k_edge(const float* __restrict__ W1,
                                                      const float* __restrict__ W2,
                                                      const float* __restrict__ b2,
                                                      const int* __restrict__ ei, int l) {
    extern __shared__ char smem[];
    ull*   sM1  = (ull*)(smem + OFF_M1);
    float* sW2  = (float*)(smem + OFF_W2);
    ull*   sRbf = (ull*)(smem + OFF_RBF);
    float* sW1C = (float*)(smem + OFF_W1C);
    float* sKt  = (float*)(smem + OFF_KT);
    float* sB2  = (float*)(smem + OFF_B2);
    int*   sDst = (int*)(smem + OFF_DST);
    int*   sSrc = (int*)(smem + OFF_SRC);
    int*   sKnd = (int*)(smem + OFF_KND);

    int tid = threadIdx.x;
    const float* W1l = W1 + (size_t)l * 160 * H;
    const float* W2l = W2 + (size_t)l * H * D;

    for (int i = tid; i < H * D; i += ETHREADS) sW2[i] = W2l[i];
    for (int i = tid; i < 16 * H; i += ETHREADS) sW1C[i] = W1l[128 * H + i];
    if (tid < 256) sKt[tid] = g_kt[l * 256 + tid];
    if (tid < 64) sB2[tid] = b2[l * D + tid];
    __syncthreads();

    // phase A mapping: cols (jp, jp+64); 8 edge groups of 16
    const int jp = tid & 63;
    const int egA = tid >> 6;
    // phase B mapping: 4 d x 4 edges (acc lanes = consecutive d pair)
    const int dq = tid & 15;
    const int egB = tid >> 4;
    const int dbase = dq * 4;
    const int ebase = egB * 4;

    // hoisted per-layer constants (f32x2 over cols jp, jp+64)
    ull w1c2[16];
#pragma unroll
    for (int g = 0; g < 16; g++)
        PACK2(w1c2[g], sW1C[g * H + jp], sW1C[g * H + jp + 64]);
    ull ktv0, ktv1;
    PACK2(ktv0, sKt[jp], sKt[jp + 64]);
    PACK2(ktv1, sKt[H + jp], sKt[H + jp + 64]);

    const int chunk = (NT + EGRID - 1) / EGRID;   // 53
    int t0 = blockIdx.x * chunk;
    int t1 = t0 + chunk; if (t1 > NT) t1 = NT;

    for (int t = t0; t < t1; t++) {
        int e0 = t * TILE_E;
        // ---- tile metadata ----
        if (tid < TILE_E) {
            int e = e0 + tid;
            bool v = e < NE;
            sSrc[tid] = v ? ei[e] : 0;
            sDst[tid] = v ? ei[NE + e] : -1;
            sKnd[tid] = v ? g_kind[e] : 0;
        }
        {
            // rbf: 512 float4 per tile; each thread handles one, duplicated store
            int e = e0 + (tid >> 2);
            float4 r = (e < NE) ? ((const float4*)g_rbf)[(size_t)t * 512 + tid]
                                : make_float4(0.f, 0.f, 0.f, 0.f);
            ull* rp = &sRbf[(size_t)tid * 4];
            PACK2(rp[0], r.x, r.x);
            PACK2(rp[1], r.y, r.y);
            PACK2(rp[2], r.z, r.z);
            PACK2(rp[3], r.w, r.w);
        }
        __syncthreads();

        // ---- phase A: m1 = silu(P[dst]+Q[src]+kt[kind]+rbf@W1c), dup store ----
        {
            const int eb = egA * 16;
            // pipeline P/Q gathers one edge ahead
            int dn0 = sDst[eb], sn0 = sSrc[eb];
            const float* Pp = g_PQ + (size_t)(dn0 < 0 ? 0 : dn0) * 256;
            const float* Qp = g_PQ + (size_t)sn0 * 256 + 128;
            float p0 = Pp[jp], p1 = Pp[jp + 64];
            float q0 = Qp[jp], q1 = Qp[jp + 64];
#pragma unroll
            for (int ee = 0; ee < 16; ee++) {
                int e = eb + ee;
                float np0 = 0.f, np1 = 0.f, nq0 = 0.f, nq1 = 0.f;
                if (ee < 15) {
                    int dnn = sDst[e + 1], snn = sSrc[e + 1];
                    const float* Pn = g_PQ + (size_t)(dnn < 0 ? 0 : dnn) * 256;
                    const float* Qn = g_PQ + (size_t)snn * 256 + 128;
                    np0 = Pn[jp]; np1 = Pn[jp + 64];
                    nq0 = Qn[jp]; nq1 = Qn[jp + 64];
                }
                ull acc;
                PACK2(acc, p0 + q0, p1 + q1);
                ADD2(acc, acc, sKnd[e] ? ktv1 : ktv0);
                const ull* rb = &sRbf[e * 16];
#pragma unroll
                for (int g = 0; g < 16; g++)
                    FMA2(acc, rb[g], w1c2[g]);
                uint32_t u0, u1; UNPK2(u0, u1, acc);
                float x0 = __uint_as_float(u0), x1 = __uint_as_float(u1);
                float s0 = __fdividef(x0, 1.f + __expf(-x0));
                float s1 = __fdividef(x1, 1.f + __expf(-x1));
                ull d0, d1;
                PACK2(d0, s0, s0);
                PACK2(d1, s1, s1);
                sM1[(size_t)e * M1P + jp] = d0;
                sM1[(size_t)e * M1P + 64 + jp] = d1;
                p0 = np0; p1 = np1; q0 = nq0; q1 = nq1;
            }
        }
        __syncthreads();

        // ---- phase B: out = b2 + m1 @ W2; RED.v4 scatter ----
        {
            const ull* m0r = &sM1[(size_t)(ebase + 0) * M1P];
            const ull* m1r = &sM1[(size_t)(ebase + 1) * M1P];
            const ull* m2r = &sM1[(size_t)(ebase + 2) * M1P];
            const ull* m3r = &sM1[(size_t)(ebase + 3) * M1P];
            ull a0x = 0, a0y = 0, a1x = 0, a1y = 0;
            ull a2x = 0, a2y = 0, a3x = 0, a3y = 0;
#pragma unroll 4
            for (int j = 0; j < H; j++) {
                ulonglong2 wv = *(const ulonglong2*)&sW2[j * D + dbase];
                ull m0 = m0r[j], m1 = m1r[j], m2 = m2r[j], m3 = m3r[j];
                FMA2(a0x, m0, wv.x); FMA2(a0y, m0, wv.y);
                FMA2(a1x, m1, wv.x); FMA2(a1y, m1, wv.y);
                FMA2(a2x, m2, wv.x); FMA2(a2y, m2, wv.y);
                FMA2(a3x, m3, wv.x); FMA2(a3y, m3, wv.y);
            }
            ulonglong2 bp = *(const ulonglong2*)&sB2[dbase];
            ADD2(a0x, a0x, bp.x); ADD2(a0y, a0y, bp.y);
            ADD2(a1x, a1x, bp.x); ADD2(a1y, a1y, bp.y);
            ADD2(a2x, a2x, bp.x); ADD2(a2y, a2y, bp.y);
            ADD2(a3x, a3x, bp.x); ADD2(a3y, a3y, bp.y);
            uint32_t w0, w1, w2, w3;
            int dn;
            dn = sDst[ebase + 0];
            if (dn >= 0) {
                UNPK2(w0, w1, a0x); UNPK2(w2, w3, a0y);
                REDV4(&g_agg[(size_t)dn * D + dbase], __uint_as_float(w0), __uint_as_float(w1),
                      __uint_as_float(w2), __uint_as_float(w3));
            }
            dn = sDst[ebase + 1];
            if (dn >= 0) {
                UNPK2(w0, w1, a1x); UNPK2(w2, w3, a1y);
                REDV4(&g_agg[(size_t)dn * D + dbase], __uint_as_float(w0), __uint_as_float(w1),
                      __uint_as_float(w2), __uint_as_float(w3));
            }
            dn = sDst[ebase + 2];
            if (dn >= 0) {
                UNPK2(w0, w1, a2x); UNPK2(w2, w3, a2y);
                REDV4(&g_agg[(size_t)dn * D + dbase], __uint_as_float(w0), __uint_as_float(w1),
                      __uint_as_float(w2), __uint_as_float(w3));
            }
            dn = sDst[ebase + 3];
            if (dn >= 0) {
                UNPK2(w0, w1, a3x); UNPK2(w2, w3, a3y);
                REDV4(&g_agg[(size_t)dn * D + dbase], __uint_as_float(w0), __uint_as_float(w1),
                      __uint_as_float(w2), __uint_as_float(w3));
            }
        }
        __syncthreads();
    }
}

// ---------------- pooling (relu fused) ----------------
__global__ void k_pool(const int* __restrict__ batch) {
    int i = blockIdx.x * blockDim.x + threadIdx.x;
    if (i >= NN * D) return;
    int n = i >> 6, d = i & 63;
    float v = fmaxf(g_h[i] + g_agg[i], 0.f);
    atomicAdd(&g_sums[batch[n] * D + d], v);
}

__global__ void k_count(const int* __restrict__ batch) {
    int n = blockIdx.x * blockDim.x + threadIdx.x;
    if (n >= NN) return;
    int b = batch[n];
    unsigned mask = __activemask();
    unsigned m = __match_any_sync(mask, b);
    int leader = __ffs(m) - 1;
    if ((threadIdx.x & 31) == leader) atomicAdd(&g_cnt[b], (float)__popc(m));
}

__global__ void k_final(const float* __restrict__ fcw, const float* __restrict__ fcb,
                        float* __restrict__ out) {
    int g = threadIdx.x;
    if (g < NG) {
        float c = fmaxf(g_cnt[g], 1.f);
        float s = 0.f;
#pragma unroll
        for (int d = 0; d < D; d++) s += g_sums[g * D + d] * fcw[d];
        out[g] = s / c + fcb[0];
    }
}

extern "C" void kernel_launch(void* const* d_in, const int* in_sizes, int n_in,
                              void* d_out, int out_size) {
    const int*   atoms = (const int*)d_in[0];
    const int*   ei    = (const int*)d_in[1];
    const float* coord = (const float*)d_in[2];
    const int*   isr   = (const int*)d_in[3];
    const int*   batch = (const int*)d_in[4];
    const float* embed = (const float*)d_in[5];
    const float* subw  = (const float*)d_in[6];
    const float* W1    = (const float*)d_in[7];
    const float* b1    = (const float*)d_in[8];
    const float* W2    = (const float*)d_in[9];
    const float* b2    = (const float*)d_in[10];
    const float* fcw   = (const float*)d_in[11];
    const float* fcb   = (const float*)d_in[12];
    float* out = (float*)d_out;

    cudaFuncSetAttribute(k_edge, cudaFuncAttributeMaxDynamicSharedMemorySize, SMEM_EDGE);

    const int T = 256;
    k_init_h<<<(NN * D + T - 1) / T, T>>>(atoms, embed);                       // launch 0
    k_edge_prep<<<(NE + 1024 + T - 1) / T, T>>>(ei, coord, isr, subw, W1, b1); // launch 1

    for (int l = 0; l < NL; l++) {
        k_nodegemm<<<NN / 16, 256>>>(W1, l);                                   // launch 2,4,6,8
        k_edge<<<EGRID, ETHREADS, SMEM_EDGE>>>(W1, W2, b2, ei, l);             // launch 3,5,7,9
    }

    k_pool<<<(NN * D + T - 1) / T, T>>>(batch);
    k_count<<<(NN + T - 1) / T, T>>>(batch);
    k_final<<<1, 64>>>(fcw, fcb, out);
}